// round 13
// baseline (speedup 1.0000x reference)
#include <cuda_runtime.h>
#include <cuda_bf16.h>
#include <cstdint>
#include <math.h>

#define BATCH 8
#define SEQ   1024
#define CDIM  1024
#define HEADS 16
#define HDIM  64
#define C3    3072
#define KDIM  1024
#define K3    3072            // augmented K (hi | lo | hi vs hi | hi | lo)
#define ATT_SCALE 0.125f
#define BH    (BATCH * HEADS)

// ---------------------------------------------------------------------------
// Scratch (__device__ globals; no allocs allowed)
// ---------------------------------------------------------------------------
__device__ float g_attn[(size_t)BATCH * SEQ * CDIM];              // attn out fp32
__device__ __nv_bfloat16 g_x_aug[(size_t)BATCH * SEQ * K3];
__device__ __nv_bfloat16 g_win_aug[(size_t)C3 * K3];
__device__ __nv_bfloat16 g_attn_aug[(size_t)BATCH * SEQ * K3];
__device__ __nv_bfloat16 g_wout_aug[(size_t)CDIM * K3];
// Split attention operands written by gemm1 epilogue:
__device__ __nv_bfloat16 g_qhi[(size_t)BH * SEQ * HDIM];   // [bh][n][d], pre-scaled
__device__ __nv_bfloat16 g_qlo[(size_t)BH * SEQ * HDIM];
__device__ __nv_bfloat16 g_khi[(size_t)BH * SEQ * HDIM];   // [bh][n][d]
__device__ __nv_bfloat16 g_klo[(size_t)BH * SEQ * HDIM];
__device__ __nv_bfloat16 g_vthi[(size_t)BH * HDIM * SEQ];  // [bh][d][n] (transposed)
__device__ __nv_bfloat16 g_vtlo[(size_t)BH * HDIM * SEQ];

// ---------------------------------------------------------------------------
// Warp-level bf16 MMA + cp.async (portable PTX, sm_80+)
// ---------------------------------------------------------------------------
__device__ __forceinline__ void mma16816(float* c, const uint32_t* a,
                                         const uint32_t* b) {
    asm volatile(
        "mma.sync.aligned.m16n8k16.row.col.f32.bf16.bf16.f32 "
        "{%0,%1,%2,%3}, {%4,%5,%6,%7}, {%8,%9}, {%0,%1,%2,%3};"
        : "+f"(c[0]), "+f"(c[1]), "+f"(c[2]), "+f"(c[3])
        : "r"(a[0]), "r"(a[1]), "r"(a[2]), "r"(a[3]), "r"(b[0]), "r"(b[1]));
}

__device__ __forceinline__ void cp_async16(__nv_bfloat16* dst,
                                           const __nv_bfloat16* src) {
    const uint32_t s = (uint32_t)__cvta_generic_to_shared(dst);
    asm volatile("cp.async.cg.shared.global [%0], [%1], 16;"
                 :: "r"(s), "l"(src) : "memory");
}
#define CP_COMMIT() asm volatile("cp.async.commit_group;" ::: "memory")
#define CP_WAIT(n)  asm volatile("cp.async.wait_group %0;" :: "n"(n) : "memory")

__device__ __forceinline__ uint32_t pack_bf2(float a, float b) {
    __nv_bfloat162 t;
    t.x = __float2bfloat16(a);
    t.y = __float2bfloat16(b);
    return *reinterpret_cast<uint32_t*>(&t);
}

// ---------------------------------------------------------------------------
// Split-precision augmentation for GEMM inputs.
// PAT 0 (A-side): [hi | lo | hi]    PAT 1 (B-side): [hi | hi | lo]
// ---------------------------------------------------------------------------
template <int PAT>
__global__ void __launch_bounds__(256) aug_kernel(
    const float* __restrict__ src, __nv_bfloat16* __restrict__ dst, int n)
{
    for (int i = blockIdx.x * blockDim.x + threadIdx.x; i < n;
         i += gridDim.x * blockDim.x) {
        const float a = src[i];
        const __nv_bfloat16 hi = __float2bfloat16(a);
        const __nv_bfloat16 lo = __float2bfloat16(a - __bfloat162float(hi));
        const int row = i >> 10;
        const int col = i & 1023;
        const size_t b = (size_t)row * K3;
        if (PAT == 0) {
            dst[b + col] = hi; dst[b + 1024 + col] = lo; dst[b + 2048 + col] = hi;
        } else {
            dst[b + col] = hi; dst[b + 1024 + col] = hi; dst[b + 2048 + col] = lo;
        }
    }
}

// ---------------------------------------------------------------------------
// HMMA GEMM with cp.async double-buffered pipeline.
// C[M,N] = A_aug[M,K3] @ B_aug[N,K3]^T + bias[N]
// CTA 128x128, 8 warps, warp tile 32x64. K chunks of 64 bf16, stride 72.
// Dynamic smem: 2 stages x (As 128x72 + Bs 128x72) bf16 = 73,728 B.
// MODE 0: row-major fp32 store.  MODE 1: split-bf16 scatter to Q/K/Vt planes.
// ---------------------------------------------------------------------------
#define SSTR   72                  // smem row stride in bf16
#define STAGE  (128 * SSTR)        // bf16 elems per matrix per stage
#define NCHUNK (K3 / 64)           // 48

template <int MODE>
__global__ void __launch_bounds__(256) gemm_mma(
    const __nv_bfloat16* __restrict__ A, const __nv_bfloat16* __restrict__ Bw,
    const float* __restrict__ bias, float* __restrict__ Cout, int Ncols)
{
    extern __shared__ __nv_bfloat16 gsm[];
    // layout: [stage][As | Bs]
    __nv_bfloat16* As0 = gsm;
    __nv_bfloat16* Bs0 = gsm + STAGE;
    __nv_bfloat16* As1 = gsm + 2 * STAGE;
    __nv_bfloat16* Bs1 = gsm + 3 * STAGE;

    const int tid  = threadIdx.x;
    const int wid  = tid >> 5;
    const int lane = tid & 31;
    const int wm   = (wid & 3) << 5;
    const int wn   = (wid >> 2) << 6;
    const int gr   = lane >> 2;
    const int qc   = (lane & 3) << 1;
    const int m0   = blockIdx.y << 7;
    const int n0   = blockIdx.x << 7;

    // Per-thread load slots: 4 x (row, col-group) covering 128 rows x 8 groups
    const int lrow[4] = { tid >> 3, (tid + 256) >> 3, (tid + 512) >> 3, (tid + 768) >> 3 };
    const int lcol    = tid & 7;

    float acc[2][8][4] = {};

    // Prologue: stage 0 loads
    #pragma unroll
    for (int i = 0; i < 4; ++i) {
        cp_async16(&As0[lrow[i] * SSTR + lcol * 8],
                   &A[(size_t)(m0 + lrow[i]) * K3 + lcol * 8]);
        cp_async16(&Bs0[lrow[i] * SSTR + lcol * 8],
                   &Bw[(size_t)(n0 + lrow[i]) * K3 + lcol * 8]);
    }
    CP_COMMIT();

    for (int ck = 0; ck < NCHUNK; ++ck) {
        __nv_bfloat16* Ac = (ck & 1) ? As1 : As0;
        __nv_bfloat16* Bc = (ck & 1) ? Bs1 : Bs0;
        if (ck + 1 < NCHUNK) {
            __nv_bfloat16* An = (ck & 1) ? As0 : As1;
            __nv_bfloat16* Bn = (ck & 1) ? Bs0 : Bs1;
            const int kc = (ck + 1) << 6;
            #pragma unroll
            for (int i = 0; i < 4; ++i) {
                cp_async16(&An[lrow[i] * SSTR + lcol * 8],
                           &A[(size_t)(m0 + lrow[i]) * K3 + kc + lcol * 8]);
                cp_async16(&Bn[lrow[i] * SSTR + lcol * 8],
                           &Bw[(size_t)(n0 + lrow[i]) * K3 + kc + lcol * 8]);
            }
            CP_COMMIT();
            CP_WAIT(1);            // current stage (ck) complete
        } else {
            CP_WAIT(0);
        }
        __syncthreads();

        #pragma unroll
        for (int ks = 0; ks < 4; ++ks) {
            const int k0 = ks << 4;
            uint32_t afr[2][4];
            #pragma unroll
            for (int mt = 0; mt < 2; ++mt) {
                const int rm = wm + (mt << 4) + gr;
                afr[mt][0] = *(const uint32_t*)&Ac[(rm    ) * SSTR + k0 + qc];
                afr[mt][1] = *(const uint32_t*)&Ac[(rm + 8) * SSTR + k0 + qc];
                afr[mt][2] = *(const uint32_t*)&Ac[(rm    ) * SSTR + k0 + qc + 8];
                afr[mt][3] = *(const uint32_t*)&Ac[(rm + 8) * SSTR + k0 + qc + 8];
            }
            #pragma unroll
            for (int nt = 0; nt < 8; ++nt) {
                const int rn = wn + (nt << 3) + gr;
                uint32_t bfr[2];
                bfr[0] = *(const uint32_t*)&Bc[rn * SSTR + k0 + qc];
                bfr[1] = *(const uint32_t*)&Bc[rn * SSTR + k0 + qc + 8];
                mma16816(acc[0][nt], afr[0], bfr);
                mma16816(acc[1][nt], afr[1], bfr);
            }
        }
        __syncthreads();           // done reading this stage before it is refilled
    }

    #pragma unroll
    for (int mt = 0; mt < 2; ++mt) {
        #pragma unroll
        for (int nt = 0; nt < 8; ++nt) {
            const int nc = n0 + wn + (nt << 3) + qc;
            const float bx = bias[nc];
            const float by = bias[nc + 1];
            #pragma unroll
            for (int h = 0; h < 2; ++h) {
                const int m = m0 + wm + (mt << 4) + gr + (h << 3);
                float vx = acc[mt][nt][h * 2 + 0] + bx;
                float vy = acc[mt][nt][h * 2 + 1] + by;
                if (MODE == 0) {
                    float2 v; v.x = vx; v.y = vy;
                    *(float2*)&Cout[(size_t)m * Ncols + nc] = v;
                } else {
                    const int which = nc >> 10;
                    const int hd    = (nc & 1023) >> 6;
                    const int d     = nc & 63;
                    const int bb    = m >> 10;
                    const int ns    = m & 1023;
                    const int bhh   = bb * HEADS + hd;
                    if (which == 0) { vx *= ATT_SCALE; vy *= ATT_SCALE; }
                    const __nv_bfloat16 hx = __float2bfloat16(vx);
                    const __nv_bfloat16 hy = __float2bfloat16(vy);
                    const __nv_bfloat16 lx = __float2bfloat16(vx - __bfloat162float(hx));
                    const __nv_bfloat16 ly = __float2bfloat16(vy - __bfloat162float(hy));
                    if (which == 2) {
                        const size_t tb = ((size_t)bhh * HDIM + d) * SEQ + ns;
                        g_vthi[tb]       = hx;  g_vthi[tb + SEQ] = hy;
                        g_vtlo[tb]       = lx;  g_vtlo[tb + SEQ] = ly;
                    } else {
                        const size_t idx = ((size_t)bhh * SEQ + ns) * HDIM + d;
                        __nv_bfloat162 h2; h2.x = hx; h2.y = hy;
                        __nv_bfloat162 l2; l2.x = lx; l2.y = ly;
                        if (which == 0) {
                            *(__nv_bfloat162*)&g_qhi[idx] = h2;
                            *(__nv_bfloat162*)&g_qlo[idx] = l2;
                        } else {
                            *(__nv_bfloat162*)&g_khi[idx] = h2;
                            *(__nv_bfloat162*)&g_klo[idx] = l2;
                        }
                    }
                }
            }
        }
    }
}

// ---------------------------------------------------------------------------
// HMMA flash attention (unchanged from passing R10 kernel).
// Grid (SEQ/128, BH), 256 threads (8 warps x 16 q-rows).
// ---------------------------------------------------------------------------
#define ASTR 72

__global__ void __launch_bounds__(256) attn_mma(float* __restrict__ out)
{
    extern __shared__ __nv_bfloat16 sb[];
    __nv_bfloat16* sQh = sb;                    // [128][72]
    __nv_bfloat16* sQl = sQh + 128 * ASTR;      // [128][72]
    __nv_bfloat16* sKh = sQl + 128 * ASTR;      // [64][72]
    __nv_bfloat16* sKl = sKh + 64 * ASTR;
    __nv_bfloat16* sVh = sKl + 64 * ASTR;       // [64][72] (rows = d)
    __nv_bfloat16* sVl = sVh + 64 * ASTR;

    const int bh  = blockIdx.y;
    const int q0  = blockIdx.x << 7;
    const int tid = threadIdx.x;
    const int wid = tid >> 5;
    const int lane = tid & 31;
    const int gr  = lane >> 2;
    const int qc  = (lane & 3) << 1;
    const int wm  = wid << 4;

    const size_t qkbase = (size_t)bh * SEQ * HDIM;
    const size_t vtbase = (size_t)bh * HDIM * SEQ;

    #pragma unroll
    for (int i = 0; i < 4; ++i) {
        const int cid = tid + (i << 8);
        const int r = cid >> 3, c = cid & 7;
        *(uint4*)&sQh[r * ASTR + c * 8] =
            *(const uint4*)&g_qhi[qkbase + (size_t)(q0 + r) * HDIM + c * 8];
        *(uint4*)&sQl[r * ASTR + c * 8] =
            *(const uint4*)&g_qlo[qkbase + (size_t)(q0 + r) * HDIM + c * 8];
    }

    float accO[8][4] = {};
    float m0r = -1e30f, m8r = -1e30f, l0r = 0.f, l8r = 0.f;
    __syncthreads();

    for (int kt = 0; kt < SEQ; kt += 64) {
        #pragma unroll
        for (int i = 0; i < 2; ++i) {
            const int cid = tid + (i << 8);
            const int r = cid >> 3, c = cid & 7;
            *(uint4*)&sKh[r * ASTR + c * 8] =
                *(const uint4*)&g_khi[qkbase + (size_t)(kt + r) * HDIM + c * 8];
            *(uint4*)&sKl[r * ASTR + c * 8] =
                *(const uint4*)&g_klo[qkbase + (size_t)(kt + r) * HDIM + c * 8];
            *(uint4*)&sVh[r * ASTR + c * 8] =
                *(const uint4*)&g_vthi[vtbase + (size_t)r * SEQ + kt + c * 8];
            *(uint4*)&sVl[r * ASTR + c * 8] =
                *(const uint4*)&g_vtlo[vtbase + (size_t)r * SEQ + kt + c * 8];
        }
        __syncthreads();

        float S[8][4];
        #pragma unroll
        for (int nt = 0; nt < 8; ++nt)
            S[nt][0] = S[nt][1] = S[nt][2] = S[nt][3] = 0.f;

        #pragma unroll
        for (int ks = 0; ks < 4; ++ks) {
            const int k0 = ks << 4;
            const int rm = wm + gr;
            uint32_t ah[4], al[4];
            ah[0] = *(const uint32_t*)&sQh[(rm    ) * ASTR + k0 + qc];
            ah[1] = *(const uint32_t*)&sQh[(rm + 8) * ASTR + k0 + qc];
            ah[2] = *(const uint32_t*)&sQh[(rm    ) * ASTR + k0 + qc + 8];
            ah[3] = *(const uint32_t*)&sQh[(rm + 8) * ASTR + k0 + qc + 8];
            al[0] = *(const uint32_t*)&sQl[(rm    ) * ASTR + k0 + qc];
            al[1] = *(const uint32_t*)&sQl[(rm + 8) * ASTR + k0 + qc];
            al[2] = *(const uint32_t*)&sQl[(rm    ) * ASTR + k0 + qc + 8];
            al[3] = *(const uint32_t*)&sQl[(rm + 8) * ASTR + k0 + qc + 8];
            #pragma unroll
            for (int nt = 0; nt < 8; ++nt) {
                const int rn = (nt << 3) + gr;
                uint32_t bhf[2], blf[2];
                bhf[0] = *(const uint32_t*)&sKh[rn * ASTR + k0 + qc];
                bhf[1] = *(const uint32_t*)&sKh[rn * ASTR + k0 + qc + 8];
                blf[0] = *(const uint32_t*)&sKl[rn * ASTR + k0 + qc];
                blf[1] = *(const uint32_t*)&sKl[rn * ASTR + k0 + qc + 8];
                mma16816(S[nt], ah, bhf);
                mma16816(S[nt], al, bhf);
                mma16816(S[nt], ah, blf);
            }
        }

        float mx0 = -1e30f, mx8 = -1e30f;
        #pragma unroll
        for (int nt = 0; nt < 8; ++nt) {
            mx0 = fmaxf(mx0, fmaxf(S[nt][0], S[nt][1]));
            mx8 = fmaxf(mx8, fmaxf(S[nt][2], S[nt][3]));
        }
        mx0 = fmaxf(mx0, __shfl_xor_sync(0xffffffffu, mx0, 1));
        mx0 = fmaxf(mx0, __shfl_xor_sync(0xffffffffu, mx0, 2));
        mx8 = fmaxf(mx8, __shfl_xor_sync(0xffffffffu, mx8, 1));
        mx8 = fmaxf(mx8, __shfl_xor_sync(0xffffffffu, mx8, 2));
        const float mn0 = fmaxf(m0r, mx0);
        const float mn8 = fmaxf(m8r, mx8);
        const float al0 = __expf(m0r - mn0);
        const float al8 = __expf(m8r - mn8);
        float sum0 = 0.f, sum8 = 0.f;
        #pragma unroll
        for (int nt = 0; nt < 8; ++nt) {
            S[nt][0] = __expf(S[nt][0] - mn0); sum0 += S[nt][0];
            S[nt][1] = __expf(S[nt][1] - mn0); sum0 += S[nt][1];
            S[nt][2] = __expf(S[nt][2] - mn8); sum8 += S[nt][2];
            S[nt][3] = __expf(S[nt][3] - mn8); sum8 += S[nt][3];
        }
        sum0 += __shfl_xor_sync(0xffffffffu, sum0, 1);
        sum0 += __shfl_xor_sync(0xffffffffu, sum0, 2);
        sum8 += __shfl_xor_sync(0xffffffffu, sum8, 1);
        sum8 += __shfl_xor_sync(0xffffffffu, sum8, 2);
        l0r = l0r * al0 + sum0;  m0r = mn0;
        l8r = l8r * al8 + sum8;  m8r = mn8;

        #pragma unroll
        for (int nt = 0; nt < 8; ++nt) {
            accO[nt][0] *= al0; accO[nt][1] *= al0;
            accO[nt][2] *= al8; accO[nt][3] *= al8;
        }
        #pragma unroll
        for (int s = 0; s < 4; ++s) {
            const int k0 = s << 4;
            uint32_t ph[4], pl[4];
            {
                const float f0 = S[2*s][0],   f1 = S[2*s][1];
                const float f2 = S[2*s][2],   f3 = S[2*s][3];
                const float g0 = S[2*s+1][0], g1 = S[2*s+1][1];
                const float g2 = S[2*s+1][2], g3 = S[2*s+1][3];
                const __nv_bfloat16 h0 = __float2bfloat16(f0), h1 = __float2bfloat16(f1);
                const __nv_bfloat16 h2 = __float2bfloat16(f2), h3 = __float2bfloat16(f3);
                const __nv_bfloat16 j0 = __float2bfloat16(g0), j1 = __float2bfloat16(g1);
                const __nv_bfloat16 j2 = __float2bfloat16(g2), j3 = __float2bfloat16(g3);
                __nv_bfloat162 t;
                t.x = h0; t.y = h1; ph[0] = *(uint32_t*)&t;
                t.x = h2; t.y = h3; ph[1] = *(uint32_t*)&t;
                t.x = j0; t.y = j1; ph[2] = *(uint32_t*)&t;
                t.x = j2; t.y = j3; ph[3] = *(uint32_t*)&t;
                pl[0] = pack_bf2(f0 - __bfloat162float(h0), f1 - __bfloat162float(h1));
                pl[1] = pack_bf2(f2 - __bfloat162float(h2), f3 - __bfloat162float(h3));
                pl[2] = pack_bf2(g0 - __bfloat162float(j0), g1 - __bfloat162float(j1));
                pl[3] = pack_bf2(g2 - __bfloat162float(j2), g3 - __bfloat162float(j3));
            }
            #pragma unroll
            for (int nt = 0; nt < 8; ++nt) {
                const int rn = (nt << 3) + gr;
                uint32_t vh[2], vl[2];
                vh[0] = *(const uint32_t*)&sVh[rn * ASTR + k0 + qc];
                vh[1] = *(const uint32_t*)&sVh[rn * ASTR + k0 + qc + 8];
                vl[0] = *(const uint32_t*)&sVl[rn * ASTR + k0 + qc];
                vl[1] = *(const uint32_t*)&sVl[rn * ASTR + k0 + qc + 8];
                mma16816(accO[nt], ph, vh);
                mma16816(accO[nt], pl, vh);
                mma16816(accO[nt], ph, vl);
            }
        }
        __syncthreads();
    }

    const float inv0 = 1.0f / l0r;
    const float inv8 = 1.0f / l8r;
    const int b = bh >> 4;
    const int h = bh & 15;
    const int r0 = q0 + wm + gr;
    #pragma unroll
    for (int nt = 0; nt < 8; ++nt) {
        const int d = h * HDIM + (nt << 3) + qc;
        float2 v0; v0.x = accO[nt][0] * inv0; v0.y = accO[nt][1] * inv0;
        float2 v8; v8.x = accO[nt][2] * inv8; v8.y = accO[nt][3] * inv8;
        *(float2*)&out[((size_t)b * SEQ + r0    ) * CDIM + d] = v0;
        *(float2*)&out[((size_t)b * SEQ + r0 + 8) * CDIM + d] = v8;
    }
}

// ---------------------------------------------------------------------------

extern "C" void kernel_launch(void* const* d_in, const int* in_sizes, int n_in,
                              void* d_out, int out_size)
{
    const float* x     = (const float*)d_in[0];
    const float* w_in  = (const float*)d_in[1];
    const float* b_in  = (const float*)d_in[2];
    const float* w_out = (const float*)d_in[3];
    const float* b_out = (const float*)d_in[4];
    float* out = (float*)d_out;

    float* attn;
    __nv_bfloat16 *xa, *wia, *ata, *woa;
    cudaGetSymbolAddress((void**)&attn, g_attn);
    cudaGetSymbolAddress((void**)&xa,  g_x_aug);
    cudaGetSymbolAddress((void**)&wia, g_win_aug);
    cudaGetSymbolAddress((void**)&ata, g_attn_aug);
    cudaGetSymbolAddress((void**)&woa, g_wout_aug);

    const int gemm_smem = 4 * STAGE * (int)sizeof(__nv_bfloat16);   // 73,728 B
    cudaFuncSetAttribute(gemm_mma<1>, cudaFuncAttributeMaxDynamicSharedMemorySize,
                         gemm_smem);
    cudaFuncSetAttribute(gemm_mma<0>, cudaFuncAttributeMaxDynamicSharedMemorySize,
                         gemm_smem);

    // 1) bf16 split-augmentation of x and w_in
    aug_kernel<0><<<4096, 256>>>(x, xa, BATCH * SEQ * KDIM);
    aug_kernel<1><<<2048, 256>>>(w_in, wia, C3 * KDIM);

    // 2) QKV projection on HMMA (cp.async pipelined); epilogue emits split planes
    gemm_mma<1><<<dim3(C3 / 128, (BATCH * SEQ) / 128), 256, gemm_smem>>>(
        xa, wia, b_in, attn /*unused*/, C3);

    // 3) HMMA flash attention
    const int att_smem = (2 * 128 + 4 * 64) * ASTR * (int)sizeof(__nv_bfloat16);
    cudaFuncSetAttribute(attn_mma, cudaFuncAttributeMaxDynamicSharedMemorySize,
                         att_smem);
    attn_mma<<<dim3(SEQ / 128, BH), 256, att_smem>>>(attn);

    // 4) Augment attention output and w_out, then output projection on HMMA
    aug_kernel<0><<<4096, 256>>>(attn, ata, BATCH * SEQ * KDIM);
    aug_kernel<1><<<1024, 256>>>(w_out, woa, CDIM * KDIM);
    gemm_mma<0><<<dim3(CDIM / 128, (BATCH * SEQ) / 128), 256, gemm_smem>>>(
        ata, woa, b_out, out, CDIM);
}

// round 16
// speedup vs baseline: 1.6958x; 1.6958x over previous
#include <cuda_runtime.h>
#include <cuda_bf16.h>
#include <cstdint>
#include <math.h>

#define BATCH 8
#define SEQ   1024
#define CDIM  1024
#define HEADS 16
#define HDIM  64
#define C3    3072
#define KDIM  1024
#define K3    3072            // augmented K (hi | lo | hi vs hi | hi | lo)
#define ATT_SCALE 0.125f
#define BH    (BATCH * HEADS)

// ---------------------------------------------------------------------------
// Scratch (__device__ globals; no allocs allowed)
// ---------------------------------------------------------------------------
__device__ float g_attn[(size_t)BATCH * SEQ * CDIM];              // attn out fp32
__device__ __nv_bfloat16 g_x_aug[(size_t)BATCH * SEQ * K3];
__device__ __nv_bfloat16 g_win_aug[(size_t)C3 * K3];
__device__ __nv_bfloat16 g_attn_aug[(size_t)BATCH * SEQ * K3];
__device__ __nv_bfloat16 g_wout_aug[(size_t)CDIM * K3];
// Split attention operands written by gemm1 epilogue:
__device__ __nv_bfloat16 g_qhi[(size_t)BH * SEQ * HDIM];   // [bh][n][d], pre-scaled
__device__ __nv_bfloat16 g_qlo[(size_t)BH * SEQ * HDIM];
__device__ __nv_bfloat16 g_khi[(size_t)BH * SEQ * HDIM];   // [bh][n][d]
__device__ __nv_bfloat16 g_klo[(size_t)BH * SEQ * HDIM];
__device__ __nv_bfloat16 g_vthi[(size_t)BH * HDIM * SEQ];  // [bh][d][n] (transposed)
__device__ __nv_bfloat16 g_vtlo[(size_t)BH * HDIM * SEQ];

// ---------------------------------------------------------------------------
// Warp-level bf16 MMA + ldmatrix (portable PTX, sm_80+)
// ---------------------------------------------------------------------------
__device__ __forceinline__ void mma16816(float* c, const uint32_t* a,
                                         const uint32_t* b) {
    asm volatile(
        "mma.sync.aligned.m16n8k16.row.col.f32.bf16.bf16.f32 "
        "{%0,%1,%2,%3}, {%4,%5,%6,%7}, {%8,%9}, {%0,%1,%2,%3};"
        : "+f"(c[0]), "+f"(c[1]), "+f"(c[2]), "+f"(c[3])
        : "r"(a[0]), "r"(a[1]), "r"(a[2]), "r"(a[3]), "r"(b[0]), "r"(b[1]));
}

__device__ __forceinline__ void ldsm_x4(uint32_t* r, uint32_t addr) {
    asm volatile(
        "ldmatrix.sync.aligned.m8n8.x4.shared.b16 {%0,%1,%2,%3}, [%4];"
        : "=r"(r[0]), "=r"(r[1]), "=r"(r[2]), "=r"(r[3]) : "r"(addr));
}
__device__ __forceinline__ void ldsm_x2(uint32_t* r, uint32_t addr) {
    asm volatile(
        "ldmatrix.sync.aligned.m8n8.x2.shared.b16 {%0,%1}, [%2];"
        : "=r"(r[0]), "=r"(r[1]) : "r"(addr));
}

__device__ __forceinline__ uint32_t pack_bf2(float a, float b) {
    __nv_bfloat162 t;
    t.x = __float2bfloat16(a);
    t.y = __float2bfloat16(b);
    return *reinterpret_cast<uint32_t*>(&t);
}

// ---------------------------------------------------------------------------
// Split-precision augmentation for GEMM inputs.
// PAT 0 (A-side): [hi | lo | hi]    PAT 1 (B-side): [hi | hi | lo]
// ---------------------------------------------------------------------------
template <int PAT>
__global__ void __launch_bounds__(256) aug_kernel(
    const float* __restrict__ src, __nv_bfloat16* __restrict__ dst, int n)
{
    for (int i = blockIdx.x * blockDim.x + threadIdx.x; i < n;
         i += gridDim.x * blockDim.x) {
        const float a = src[i];
        const __nv_bfloat16 hi = __float2bfloat16(a);
        const __nv_bfloat16 lo = __float2bfloat16(a - __bfloat162float(hi));
        const int row = i >> 10;
        const int col = i & 1023;
        const size_t b = (size_t)row * K3;
        if (PAT == 0) {
            dst[b + col] = hi; dst[b + 1024 + col] = lo; dst[b + 2048 + col] = hi;
        } else {
            dst[b + col] = hi; dst[b + 1024 + col] = hi; dst[b + 2048 + col] = lo;
        }
    }
}

// ---------------------------------------------------------------------------
// HMMA GEMM (R10 sync-staging structure + ldmatrix fragment loads).
// C[M,N] = A_aug[M,K3] @ B_aug[N,K3]^T + bias[N]
// CTA 128x128, 8 warps, warp tile 32x64. K chunks of 64 bf16, stride 72.
// MODE 0: row-major fp32 store.  MODE 1: split-bf16 scatter to Q/K/Vt planes.
// ---------------------------------------------------------------------------
#define SSTR 72   // smem row stride in bf16 (144B: ldmatrix rows conflict-free)

template <int MODE>
__global__ void __launch_bounds__(256) gemm_mma(
    const __nv_bfloat16* __restrict__ A, const __nv_bfloat16* __restrict__ Bw,
    const float* __restrict__ bias, float* __restrict__ Cout, int Ncols)
{
    __shared__ __nv_bfloat16 As[128 * SSTR];
    __shared__ __nv_bfloat16 Bs[128 * SSTR];

    const int tid  = threadIdx.x;
    const int wid  = tid >> 5;
    const int lane = tid & 31;
    const int wm   = (wid & 3) << 5;
    const int wn   = (wid >> 2) << 6;
    const int gr   = lane >> 2;
    const int qc   = (lane & 3) << 1;
    const int m0   = blockIdx.y << 7;
    const int n0   = blockIdx.x << 7;

    const uint32_t aBase = (uint32_t)__cvta_generic_to_shared(As);
    const uint32_t bBase = (uint32_t)__cvta_generic_to_shared(Bs);
    // ldmatrix per-lane source row/col (A: x4 over 16 rows x 16 cols)
    const int arow = lane & 15;
    const int acol = (lane >> 4) << 3;         // 0 or 8
    // (B: x2 over 8 rows x 16 cols; lanes 16-31 mirror 0-15)
    const int brow = lane & 7;
    const int bcol = ((lane >> 3) & 1) << 3;   // 0 or 8

    float acc[2][8][4] = {};

    for (int kc = 0; kc < K3; kc += 64) {
        #pragma unroll
        for (int i = 0; i < 4; ++i) {
            const int cid = tid + (i << 8);
            const int r   = cid >> 3;
            const int c   = cid & 7;
            *(uint4*)&As[r * SSTR + c * 8] =
                *(const uint4*)&A[(size_t)(m0 + r) * K3 + kc + c * 8];
            *(uint4*)&Bs[r * SSTR + c * 8] =
                *(const uint4*)&Bw[(size_t)(n0 + r) * K3 + kc + c * 8];
        }
        __syncthreads();

        #pragma unroll
        for (int ks = 0; ks < 4; ++ks) {
            const int k0 = ks << 4;
            uint32_t afr[2][4];
            #pragma unroll
            for (int mt = 0; mt < 2; ++mt)
                ldsm_x4(afr[mt],
                        aBase + ((wm + (mt << 4) + arow) * SSTR + k0 + acol) * 2);
            #pragma unroll
            for (int nt = 0; nt < 8; ++nt) {
                uint32_t bfr[2];
                ldsm_x2(bfr, bBase + ((wn + (nt << 3) + brow) * SSTR + k0 + bcol) * 2);
                mma16816(acc[0][nt], afr[0], bfr);
                mma16816(acc[1][nt], afr[1], bfr);
            }
        }
        __syncthreads();
    }

    #pragma unroll
    for (int mt = 0; mt < 2; ++mt) {
        #pragma unroll
        for (int nt = 0; nt < 8; ++nt) {
            const int nc = n0 + wn + (nt << 3) + qc;
            const float bx = bias[nc];
            const float by = bias[nc + 1];
            #pragma unroll
            for (int h = 0; h < 2; ++h) {
                const int m = m0 + wm + (mt << 4) + gr + (h << 3);
                float vx = acc[mt][nt][h * 2 + 0] + bx;
                float vy = acc[mt][nt][h * 2 + 1] + by;
                if (MODE == 0) {
                    float2 v; v.x = vx; v.y = vy;
                    *(float2*)&Cout[(size_t)m * Ncols + nc] = v;
                } else {
                    const int which = nc >> 10;
                    const int hd    = (nc & 1023) >> 6;
                    const int d     = nc & 63;
                    const int bb    = m >> 10;
                    const int ns    = m & 1023;
                    const int bhh   = bb * HEADS + hd;
                    if (which == 0) { vx *= ATT_SCALE; vy *= ATT_SCALE; }
                    const __nv_bfloat16 hx = __float2bfloat16(vx);
                    const __nv_bfloat16 hy = __float2bfloat16(vy);
                    const __nv_bfloat16 lx = __float2bfloat16(vx - __bfloat162float(hx));
                    const __nv_bfloat16 ly = __float2bfloat16(vy - __bfloat162float(hy));
                    if (which == 2) {
                        const size_t tb = ((size_t)bhh * HDIM + d) * SEQ + ns;
                        g_vthi[tb]       = hx;  g_vthi[tb + SEQ] = hy;
                        g_vtlo[tb]       = lx;  g_vtlo[tb + SEQ] = ly;
                    } else {
                        const size_t idx = ((size_t)bhh * SEQ + ns) * HDIM + d;
                        __nv_bfloat162 h2; h2.x = hx; h2.y = hy;
                        __nv_bfloat162 l2; l2.x = lx; l2.y = ly;
                        if (which == 0) {
                            *(__nv_bfloat162*)&g_qhi[idx] = h2;
                            *(__nv_bfloat162*)&g_qlo[idx] = l2;
                        } else {
                            *(__nv_bfloat162*)&g_khi[idx] = h2;
                            *(__nv_bfloat162*)&g_klo[idx] = l2;
                        }
                    }
                }
            }
        }
    }
}

// ---------------------------------------------------------------------------
// HMMA flash attention (R10 structure + ldmatrix fragment loads).
// Grid (SEQ/128, BH), 256 threads (8 warps x 16 q-rows).
// ---------------------------------------------------------------------------
#define ASTR 72

__global__ void __launch_bounds__(256) attn_mma(float* __restrict__ out)
{
    extern __shared__ __nv_bfloat16 sb[];
    __nv_bfloat16* sQh = sb;                    // [128][72]
    __nv_bfloat16* sQl = sQh + 128 * ASTR;      // [128][72]
    __nv_bfloat16* sKh = sQl + 128 * ASTR;      // [64][72]
    __nv_bfloat16* sKl = sKh + 64 * ASTR;
    __nv_bfloat16* sVh = sKl + 64 * ASTR;       // [64][72] (rows = d)
    __nv_bfloat16* sVl = sVh + 64 * ASTR;

    const int bh  = blockIdx.y;
    const int q0  = blockIdx.x << 7;
    const int tid = threadIdx.x;
    const int wid = tid >> 5;
    const int lane = tid & 31;
    const int gr  = lane >> 2;
    const int qc  = (lane & 3) << 1;
    const int wm  = wid << 4;

    const uint32_t sqh = (uint32_t)__cvta_generic_to_shared(sQh);
    const uint32_t sql = (uint32_t)__cvta_generic_to_shared(sQl);
    const uint32_t skh = (uint32_t)__cvta_generic_to_shared(sKh);
    const uint32_t skl = (uint32_t)__cvta_generic_to_shared(sKl);
    const uint32_t svh = (uint32_t)__cvta_generic_to_shared(sVh);
    const uint32_t svl = (uint32_t)__cvta_generic_to_shared(sVl);
    const int arow = lane & 15;
    const int acol = (lane >> 4) << 3;
    const int brow = lane & 7;
    const int bcol = ((lane >> 3) & 1) << 3;

    const size_t qkbase = (size_t)bh * SEQ * HDIM;
    const size_t vtbase = (size_t)bh * HDIM * SEQ;

    #pragma unroll
    for (int i = 0; i < 4; ++i) {
        const int cid = tid + (i << 8);
        const int r = cid >> 3, c = cid & 7;
        *(uint4*)&sQh[r * ASTR + c * 8] =
            *(const uint4*)&g_qhi[qkbase + (size_t)(q0 + r) * HDIM + c * 8];
        *(uint4*)&sQl[r * ASTR + c * 8] =
            *(const uint4*)&g_qlo[qkbase + (size_t)(q0 + r) * HDIM + c * 8];
    }

    float accO[8][4] = {};
    float m0r = -1e30f, m8r = -1e30f, l0r = 0.f, l8r = 0.f;
    __syncthreads();

    for (int kt = 0; kt < SEQ; kt += 64) {
        #pragma unroll
        for (int i = 0; i < 2; ++i) {
            const int cid = tid + (i << 8);
            const int r = cid >> 3, c = cid & 7;
            *(uint4*)&sKh[r * ASTR + c * 8] =
                *(const uint4*)&g_khi[qkbase + (size_t)(kt + r) * HDIM + c * 8];
            *(uint4*)&sKl[r * ASTR + c * 8] =
                *(const uint4*)&g_klo[qkbase + (size_t)(kt + r) * HDIM + c * 8];
            *(uint4*)&sVh[r * ASTR + c * 8] =
                *(const uint4*)&g_vthi[vtbase + (size_t)r * SEQ + kt + c * 8];
            *(uint4*)&sVl[r * ASTR + c * 8] =
                *(const uint4*)&g_vtlo[vtbase + (size_t)r * SEQ + kt + c * 8];
        }
        __syncthreads();

        float S[8][4];
        #pragma unroll
        for (int nt = 0; nt < 8; ++nt)
            S[nt][0] = S[nt][1] = S[nt][2] = S[nt][3] = 0.f;

        #pragma unroll
        for (int ks = 0; ks < 4; ++ks) {
            const int k0 = ks << 4;
            uint32_t ah[4], al[4];
            ldsm_x4(ah, sqh + ((wm + arow) * ASTR + k0 + acol) * 2);
            ldsm_x4(al, sql + ((wm + arow) * ASTR + k0 + acol) * 2);
            #pragma unroll
            for (int nt = 0; nt < 8; ++nt) {
                uint32_t bhf[2], blf[2];
                ldsm_x2(bhf, skh + (((nt << 3) + brow) * ASTR + k0 + bcol) * 2);
                ldsm_x2(blf, skl + (((nt << 3) + brow) * ASTR + k0 + bcol) * 2);
                mma16816(S[nt], ah, bhf);
                mma16816(S[nt], al, bhf);
                mma16816(S[nt], ah, blf);
            }
        }

        float mx0 = -1e30f, mx8 = -1e30f;
        #pragma unroll
        for (int nt = 0; nt < 8; ++nt) {
            mx0 = fmaxf(mx0, fmaxf(S[nt][0], S[nt][1]));
            mx8 = fmaxf(mx8, fmaxf(S[nt][2], S[nt][3]));
        }
        mx0 = fmaxf(mx0, __shfl_xor_sync(0xffffffffu, mx0, 1));
        mx0 = fmaxf(mx0, __shfl_xor_sync(0xffffffffu, mx0, 2));
        mx8 = fmaxf(mx8, __shfl_xor_sync(0xffffffffu, mx8, 1));
        mx8 = fmaxf(mx8, __shfl_xor_sync(0xffffffffu, mx8, 2));
        const float mn0 = fmaxf(m0r, mx0);
        const float mn8 = fmaxf(m8r, mx8);
        const float al0 = __expf(m0r - mn0);
        const float al8 = __expf(m8r - mn8);
        float sum0 = 0.f, sum8 = 0.f;
        #pragma unroll
        for (int nt = 0; nt < 8; ++nt) {
            S[nt][0] = __expf(S[nt][0] - mn0); sum0 += S[nt][0];
            S[nt][1] = __expf(S[nt][1] - mn0); sum0 += S[nt][1];
            S[nt][2] = __expf(S[nt][2] - mn8); sum8 += S[nt][2];
            S[nt][3] = __expf(S[nt][3] - mn8); sum8 += S[nt][3];
        }
        sum0 += __shfl_xor_sync(0xffffffffu, sum0, 1);
        sum0 += __shfl_xor_sync(0xffffffffu, sum0, 2);
        sum8 += __shfl_xor_sync(0xffffffffu, sum8, 1);
        sum8 += __shfl_xor_sync(0xffffffffu, sum8, 2);
        l0r = l0r * al0 + sum0;  m0r = mn0;
        l8r = l8r * al8 + sum8;  m8r = mn8;

        #pragma unroll
        for (int nt = 0; nt < 8; ++nt) {
            accO[nt][0] *= al0; accO[nt][1] *= al0;
            accO[nt][2] *= al8; accO[nt][3] *= al8;
        }
        #pragma unroll
        for (int s = 0; s < 4; ++s) {
            const int k0 = s << 4;
            uint32_t ph[4], pl[4];
            {
                const float f0 = S[2*s][0],   f1 = S[2*s][1];
                const float f2 = S[2*s][2],   f3 = S[2*s][3];
                const float g0 = S[2*s+1][0], g1 = S[2*s+1][1];
                const float g2 = S[2*s+1][2], g3 = S[2*s+1][3];
                const __nv_bfloat16 h0 = __float2bfloat16(f0), h1 = __float2bfloat16(f1);
                const __nv_bfloat16 h2 = __float2bfloat16(f2), h3 = __float2bfloat16(f3);
                const __nv_bfloat16 j0 = __float2bfloat16(g0), j1 = __float2bfloat16(g1);
                const __nv_bfloat16 j2 = __float2bfloat16(g2), j3 = __float2bfloat16(g3);
                __nv_bfloat162 t;
                t.x = h0; t.y = h1; ph[0] = *(uint32_t*)&t;
                t.x = h2; t.y = h3; ph[1] = *(uint32_t*)&t;
                t.x = j0; t.y = j1; ph[2] = *(uint32_t*)&t;
                t.x = j2; t.y = j3; ph[3] = *(uint32_t*)&t;
                pl[0] = pack_bf2(f0 - __bfloat162float(h0), f1 - __bfloat162float(h1));
                pl[1] = pack_bf2(f2 - __bfloat162float(h2), f3 - __bfloat162float(h3));
                pl[2] = pack_bf2(g0 - __bfloat162float(j0), g1 - __bfloat162float(j1));
                pl[3] = pack_bf2(g2 - __bfloat162float(j2), g3 - __bfloat162float(j3));
            }
            #pragma unroll
            for (int nt = 0; nt < 8; ++nt) {
                uint32_t vh[2], vl[2];
                ldsm_x2(vh, svh + (((nt << 3) + brow) * ASTR + k0 + bcol) * 2);
                ldsm_x2(vl, svl + (((nt << 3) + brow) * ASTR + k0 + bcol) * 2);
                mma16816(accO[nt], ph, vh);
                mma16816(accO[nt], pl, vh);
                mma16816(accO[nt], ph, vl);
            }
        }
        __syncthreads();
    }

    const float inv0 = 1.0f / l0r;
    const float inv8 = 1.0f / l8r;
    const int b = bh >> 4;
    const int h = bh & 15;
    const int r0 = q0 + wm + gr;
    #pragma unroll
    for (int nt = 0; nt < 8; ++nt) {
        const int d = h * HDIM + (nt << 3) + qc;
        float2 v0; v0.x = accO[nt][0] * inv0; v0.y = accO[nt][1] * inv0;
        float2 v8; v8.x = accO[nt][2] * inv8; v8.y = accO[nt][3] * inv8;
        *(float2*)&out[((size_t)b * SEQ + r0    ) * CDIM + d] = v0;
        *(float2*)&out[((size_t)b * SEQ + r0 + 8) * CDIM + d] = v8;
    }
}

// ---------------------------------------------------------------------------

extern "C" void kernel_launch(void* const* d_in, const int* in_sizes, int n_in,
                              void* d_out, int out_size)
{
    const float* x     = (const float*)d_in[0];
    const float* w_in  = (const float*)d_in[1];
    const float* b_in  = (const float*)d_in[2];
    const float* w_out = (const float*)d_in[3];
    const float* b_out = (const float*)d_in[4];
    float* out = (float*)d_out;

    float* attn;
    __nv_bfloat16 *xa, *wia, *ata, *woa;
    cudaGetSymbolAddress((void**)&attn, g_attn);
    cudaGetSymbolAddress((void**)&xa,  g_x_aug);
    cudaGetSymbolAddress((void**)&wia, g_win_aug);
    cudaGetSymbolAddress((void**)&ata, g_attn_aug);
    cudaGetSymbolAddress((void**)&woa, g_wout_aug);

    // 1) bf16 split-augmentation of x and w_in
    aug_kernel<0><<<4096, 256>>>(x, xa, BATCH * SEQ * KDIM);
    aug_kernel<1><<<2048, 256>>>(w_in, wia, C3 * KDIM);

    // 2) QKV projection on HMMA; epilogue emits split Q/K/Vt planes
    gemm_mma<1><<<dim3(C3 / 128, (BATCH * SEQ) / 128), 256>>>(
        xa, wia, b_in, attn /*unused*/, C3);

    // 3) HMMA flash attention
    const int att_smem = (2 * 128 + 4 * 64) * ASTR * (int)sizeof(__nv_bfloat16);
    cudaFuncSetAttribute(attn_mma, cudaFuncAttributeMaxDynamicSharedMemorySize,
                         att_smem);
    attn_mma<<<dim3(SEQ / 128, BH), 256, att_smem>>>(attn);

    // 4) Augment attention output and w_out, then output projection on HMMA
    aug_kernel<0><<<4096, 256>>>(attn, ata, BATCH * SEQ * KDIM);
    aug_kernel<1><<<1024, 256>>>(w_out, woa, CDIM * KDIM);
    gemm_mma<0><<<dim3(CDIM / 128, (BATCH * SEQ) / 128), 256>>>(
        ata, woa, b_out, out, CDIM);
}